// round 6
// baseline (speedup 1.0000x reference)
#include <cuda_runtime.h>
#include <math.h>

// Problem constants
#define B_TOT 256
#define AIN   8
#define MUL   1024
#define NK    20
#define NO    16
#define NTHR  320
#define PL    1040          // x-plane stride in floats (16B aligned, conflict-free)

// Persistent scratch (device globals; allocation-free)
__device__ __align__(16) float g_c[NK * MUL];
__device__ __align__(16) float g_b[NK * MUL];
__device__ __align__(16) float g_bpart[16 * NK * MUL];
__device__ __align__(16) float g_wv[B_TOT * NK * AIN];
__device__ __align__(16) float g_xt[B_TOT * MUL * AIN];   // x transposed [b][a][m]
__device__ unsigned g_cnt = 0;
__device__ unsigned g_rel = 0;

// Packed f32x2 FMA
#define FMA2(acc, a, b) \
    asm("fma.rn.f32x2 %0, %1, %2, %0;" : "+l"(acc) : "l"(a), "l"(b))

__device__ __forceinline__ float pair_sum(unsigned long long u) {
    float lo = __uint_as_float((unsigned)(u & 0xffffffffu));
    float hi = __uint_as_float((unsigned)(u >> 32));
    return lo + hi;
}

#define WARP_RED_SUM(v)                                   \
  do {                                                    \
    v += __shfl_xor_sync(0xffffffffu, v, 16);             \
    v += __shfl_xor_sync(0xffffffffu, v, 8);              \
    v += __shfl_xor_sync(0xffffffffu, v, 4);              \
    v += __shfl_xor_sync(0xffffffffu, v, 2);              \
    v += __shfl_xor_sync(0xffffffffu, v, 1);              \
  } while (0)

// Replay-safe grid barrier (all 256 blocks co-resident: 2 blocks/SM, 296 slots).
// Counter is reset by the last arriver BEFORE the release bump, so g_cnt is 0
// again at kernel exit; g_rel grows monotonically (equality test, wrap-safe).
__device__ __forceinline__ void grid_barrier() {
    __threadfence();
    __syncthreads();
    if (threadIdx.x == 0) {
        unsigned r0;
        asm volatile("ld.acquire.gpu.u32 %0, [%1];" : "=r"(r0) : "l"(&g_rel));
        unsigned old = atomicAdd(&g_cnt, 1);
        if (old == B_TOT - 1) {
            atomicExch(&g_cnt, 0);
            __threadfence();
            atomicAdd(&g_rel, 1);
        } else {
            unsigned r;
            do {
                __nanosleep(64);
                asm volatile("ld.acquire.gpu.u32 %0, [%1];" : "=r"(r) : "l"(&g_rel));
            } while (r == r0);
        }
        __threadfence();
    }
    __syncthreads();
}

// Shared-memory layout (floats), total 12283 <= 12288 (48 KB dynamic):
//   [0)      xsm (prep, 1024x9=9216) / xs planes (F, 8x1040=8320) / U chunk (5376)
//   [9216)   wsm   (2560)  -- W staged once in prep, persists all phases
//   [11776)  ysm   (160)   / y0 (8)
//   [11936)  ssm   (320)
//   [12256)  csm   (16)
//   [12272)  red   (10) + bc (1)
#define OFF_W   9216
#define OFF_Y   11776
#define OFF_S   11936
#define OFF_C   12256
#define OFF_R   12272

// ---------------------------------------------------------------------------
// U phase: partial[m,k] over a 16-batch slice; block B -> (m-tile B&15, slice B>>4)
// ---------------------------------------------------------------------------
__device__ __forceinline__ void update_phase(float* sm, const float* __restrict__ x,
                                             int B, int tid)
{
    float* xsU = sm;               // [8][512]
    float* wvs = sm + 4096;        // [8][160]
    const int m0    = (B & 15) * 64;
    const int bbase = (B >> 4) * 16;
    const int mi4   = tid / NK;
    const int k     = tid % NK;

    unsigned long long acc[4];
    #pragma unroll
    for (int i = 0; i < 4; i++) acc[i] = 0ull;

    for (int c0 = 0; c0 < 16; c0 += 8) {
        __syncthreads();
        for (int i = tid; i < 1024; i += NTHR) {
            int bi = i >> 7, rr = i & 127;
            ((float4*)(xsU + bi * 512))[rr] =
                ((const float4*)(x + (size_t)(bbase + c0 + bi) * 8192 + m0 * 8))[rr];
        }
        for (int i = tid; i < 320; i += NTHR) {
            int bi = i / 40, rr = i % 40;
            ((float4*)(wvs + bi * 160))[rr] =
                ((const float4*)(g_wv + (size_t)(bbase + c0 + bi) * 160))[rr];
        }
        __syncthreads();

        #pragma unroll
        for (int bi = 0; bi < 8; bi++) {
            const ulonglong2* wp = (const ulonglong2*)(wvs + bi * 160 + k * AIN);
            ulonglong2 wA = wp[0], wB = wp[1];
            const ulonglong2* xp = (const ulonglong2*)(xsU + bi * 512 + mi4 * 32);
            #pragma unroll
            for (int mm = 0; mm < 4; mm++) {
                ulonglong2 xA = xp[mm * 2];
                ulonglong2 xB = xp[mm * 2 + 1];
                FMA2(acc[mm], xA.x, wA.x);
                FMA2(acc[mm], xA.y, wA.y);
                FMA2(acc[mm], xB.x, wB.x);
                FMA2(acc[mm], xB.y, wB.y);
            }
        }
    }

    float* dst = g_bpart + (size_t)(B >> 4) * (NK * MUL) + k * MUL + m0 + mi4 * 4;
    #pragma unroll
    for (int mm = 0; mm < 4; mm++) dst[mm] = pair_sum(acc[mm]) * (1.0f / 256.0f);
}

// ---------------------------------------------------------------------------
// Softmax phase: blocks 0..19 (k = B). Combine 16 partials -> b, softmax over m.
// ---------------------------------------------------------------------------
__device__ __forceinline__ void softmax_phase(float* sm, int B, int tid, int accum)
{
    if (B >= NK) return;
    const int k = B;
    float* red = sm + OFF_R;       // [10]
    float* bcp = sm + OFF_R + 10;
    const int lane = tid & 31, wp = tid >> 5;

    float v[4];
    #pragma unroll
    for (int i = 0; i < 4; i++) {
        int m = tid + i * NTHR;
        if (m < MUL) {
            float b = accum ? g_b[k * MUL + m] : 0.f;
            #pragma unroll
            for (int p = 0; p < 16; p++) b += g_bpart[p * NK * MUL + k * MUL + m];
            g_b[k * MUL + m] = b;
            v[i] = b;
        } else v[i] = -3.4e38f;
    }

    float mx = fmaxf(fmaxf(v[0], v[1]), fmaxf(v[2], v[3]));
    #pragma unroll
    for (int off = 16; off; off >>= 1)
        mx = fmaxf(mx, __shfl_xor_sync(0xffffffffu, mx, off));
    if (lane == 0) red[wp] = mx;
    __syncthreads();
    if (tid == 0) {
        float m = red[0];
        #pragma unroll
        for (int i = 1; i < 10; i++) m = fmaxf(m, red[i]);
        *bcp = m;
    }
    __syncthreads();
    mx = *bcp;

    float s = 0.f;
    #pragma unroll
    for (int i = 0; i < 4; i++) {
        int m = tid + i * NTHR;
        if (m < MUL) { v[i] = expf(v[i] - mx); s += v[i]; }
    }
    #pragma unroll
    for (int off = 16; off; off >>= 1)
        s += __shfl_xor_sync(0xffffffffu, s, off);
    __syncthreads();
    if (lane == 0) red[wp] = s;
    __syncthreads();
    if (tid == 0) {
        float ss = 0.f;
        #pragma unroll
        for (int i = 0; i < 10; i++) ss += red[i];
        *bcp = ss;
    }
    __syncthreads();
    float inv = 1.0f / *bcp;
    #pragma unroll
    for (int i = 0; i < 4; i++) {
        int m = tid + i * NTHR;
        if (m < MUL) g_c[k * MUL + m] = v[i] * inv;
    }
}

// ---------------------------------------------------------------------------
// F phase (iterations 1,2): y = c^T x, s = W y, v = squash(s), wv or output.
// warp = class-pair (10 warps x 2 classes); acc[2][8] u64 = 32 regs, NO SPILL.
// ---------------------------------------------------------------------------
__device__ __forceinline__ void fused_phase(float* sm, float* __restrict__ out,
                                            int B, int tid, int final_iter)
{
    float* xs  = sm;               // planes [a][PL]
    float* wsm = sm + OFF_W;
    float* ysm = sm + OFF_Y;       // [NK][AIN]
    float* ssm = sm + OFF_S;       // [NK*NO]
    float* csm = sm + OFF_C;       // [NO]

    // stage x planes from pre-transposed g_xt (pure float4 copy)
    {
        const float4* xsrc = (const float4*)(g_xt + (size_t)B * 8192);
        for (int i = tid; i < 2048; i += NTHR) {
            int a = i >> 8, q = i & 255;
            *(float4*)(xs + a * PL + q * 4) = xsrc[i];
        }
    }
    __syncthreads();

    // y phase
    {
        const int w = tid >> 5, lane = tid & 31;
        const int k0 = w * 2;
        unsigned long long acc[2][8];
        #pragma unroll
        for (int kk = 0; kk < 2; kk++)
            #pragma unroll
            for (int a = 0; a < 8; a++) acc[kk][a] = 0ull;

        #pragma unroll
        for (int j = 0; j < 8; j++) {
            const int m = j * 128 + lane * 4;
            ulonglong2 c0 = *(const ulonglong2*)(g_c + (k0 + 0) * MUL + m);
            ulonglong2 c1 = *(const ulonglong2*)(g_c + (k0 + 1) * MUL + m);
            #pragma unroll
            for (int a = 0; a < 8; a++) {
                ulonglong2 xv = *(const ulonglong2*)(xs + a * PL + m);
                FMA2(acc[0][a], c0.x, xv.x); FMA2(acc[0][a], c0.y, xv.y);
                FMA2(acc[1][a], c1.x, xv.x); FMA2(acc[1][a], c1.y, xv.y);
            }
        }
        #pragma unroll
        for (int kk = 0; kk < 2; kk++) {
            #pragma unroll
            for (int a = 0; a < 8; a++) {
                float v = pair_sum(acc[kk][a]);
                WARP_RED_SUM(v);
                if (lane == 0) ysm[(k0 + kk) * AIN + a] = v;
            }
        }
    }
    __syncthreads();

    // s / squash / v / wv
    const int k = tid >> 4, o = tid & 15;
    const float* wk = wsm + (k * NO + o) * AIN;
    const float* yk = ysm + k * AIN;
    float s = 0.f;
    #pragma unroll
    for (int a = 0; a < AIN; a++) s += wk[a] * yk[a];
    ssm[tid] = s;
    __syncthreads();

    if (tid < NO) {
        float msq = 0.f;
        #pragma unroll
        for (int kk = 0; kk < NK; kk++) {
            float t = ssm[kk * NO + tid];
            msq += t * t;
        }
        csm[tid] = msq / ((1.f + msq) * sqrtf(msq));
    }
    __syncthreads();

    float v = csm[o] * s;
    if (final_iter) out[(size_t)B * (NK * NO) + tid] = v;
    ssm[tid] = v;
    __syncthreads();

    if (!final_iter && tid < NK * AIN) {
        int kk = tid >> 3, aa = tid & 7;
        float acc = 0.f;
        #pragma unroll
        for (int oo = 0; oo < NO; oo++)
            acc += wsm[(kk * NO + oo) * AIN + aa] * ssm[kk * NO + oo];
        g_wv[(size_t)B * (NK * AIN) + tid] = acc;
    }
}

// ---------------------------------------------------------------------------
// Single persistent kernel: prep+iter0, U0, S0, F1, U1, S1, F2.
// ---------------------------------------------------------------------------
__global__ void __launch_bounds__(NTHR, 2)
capsule_persistent(const float* __restrict__ x, const float* __restrict__ W,
                   float* __restrict__ out)
{
    extern __shared__ float sm[];
    const int tid = threadIdx.x;
    const int B   = blockIdx.x;

    // ===== Phase P: prep (transpose x -> g_xt) + full iteration 0 =====
    {
        float* xsm = sm;                 // [1024][9]
        float* wsm = sm + OFF_W;
        float* y0  = sm + OFF_Y;
        float* ssm = sm + OFF_S;
        float* csm = sm + OFF_C;

        const float4* xsrc = (const float4*)(x + (size_t)B * 8192);
        for (int i = tid; i < 2048; i += NTHR) {
            float4 v = xsrc[i];
            int m = i >> 1, h = i & 1;
            float* d = xsm + m * 9 + h * 4;
            d[0] = v.x; d[1] = v.y; d[2] = v.z; d[3] = v.w;
        }
        for (int i = tid; i < 640; i += NTHR)
            ((float4*)wsm)[i] = ((const float4*)W)[i];
        __syncthreads();

        float4* xdst = (float4*)(g_xt + (size_t)B * 8192);
        for (int i = tid; i < 2048; i += NTHR) {
            int a = i >> 8, q = i & 255, m4 = q * 4;
            float4 v;
            v.x = xsm[(m4 + 0) * 9 + a];
            v.y = xsm[(m4 + 1) * 9 + a];
            v.z = xsm[(m4 + 2) * 9 + a];
            v.w = xsm[(m4 + 3) * 9 + a];
            xdst[a * 256 + q] = v;
        }

        {
            int w = tid >> 5, lane = tid & 31;
            if (w < 8) {
                float s = 0.f;
                #pragma unroll 8
                for (int t = 0; t < 32; t++) s += xsm[(t * 32 + lane) * 9 + w];
                WARP_RED_SUM(s);
                if (lane == 0) y0[w] = s * (1.0f / 1024.0f);
            }
        }
        __syncthreads();

        const int k = tid >> 4, o = tid & 15;
        const float* wk = wsm + (k * NO + o) * AIN;
        float s = 0.f;
        #pragma unroll
        for (int a = 0; a < AIN; a++) s += wk[a] * y0[a];
        ssm[tid] = s;
        __syncthreads();

        if (tid < NO) {
            float msq = 0.f;
            #pragma unroll
            for (int kk = 0; kk < NK; kk++) {
                float t = ssm[kk * NO + tid];
                msq += t * t;
            }
            csm[tid] = msq / ((1.f + msq) * sqrtf(msq));
        }
        __syncthreads();

        float v = csm[o] * s;
        ssm[tid] = v;
        __syncthreads();

        if (tid < NK * AIN) {
            int kk = tid >> 3, aa = tid & 7;
            float acc = 0.f;
            #pragma unroll
            for (int oo = 0; oo < NO; oo++)
                acc += wsm[(kk * NO + oo) * AIN + aa] * ssm[kk * NO + oo];
            g_wv[(size_t)B * (NK * AIN) + tid] = acc;
        }
    }

    grid_barrier();
    update_phase(sm, x, B, tid);
    grid_barrier();
    softmax_phase(sm, B, tid, 0);
    grid_barrier();
    fused_phase(sm, out, B, tid, 0);
    grid_barrier();
    update_phase(sm, x, B, tid);
    grid_barrier();
    softmax_phase(sm, B, tid, 1);
    grid_barrier();
    fused_phase(sm, out, B, tid, 1);
}

// ---------------------------------------------------------------------------
extern "C" void kernel_launch(void* const* d_in, const int* in_sizes, int n_in,
                              void* d_out, int out_size)
{
    const float* x = (const float*)d_in[0];   // [256][1024][8] flat view
    const float* W = (const float*)d_in[1];   // [20][16][8]
    float* out = (float*)d_out;               // [256][20][16][1]

    const int SMEM = 12288 * (int)sizeof(float);   // 48 KB dynamic
    cudaFuncSetAttribute(capsule_persistent,
                         cudaFuncAttributeMaxDynamicSharedMemorySize, SMEM);

    capsule_persistent<<<B_TOT, NTHR, SMEM>>>(x, W, out);
}

// round 7
// speedup vs baseline: 1.1999x; 1.1999x over previous
#include <cuda_runtime.h>
#include <math.h>

// Problem constants
#define B_TOT 256
#define AIN   8
#define MUL   1024
#define NK    20
#define NO    16
#define PL    1040          // x-plane stride in floats (conflict-free, 16B aligned)

// Persistent scratch (device globals; allocation-free)
__device__ __align__(16) float g_c[NK * MUL];
__device__ __align__(16) float g_b[NK * MUL];
__device__ __align__(16) float g_bpart[16 * NK * MUL];
__device__ __align__(16) float g_wv[B_TOT * NK * AIN];
__device__ __align__(16) float g_xt[B_TOT * MUL * AIN];   // x transposed [b][a][m]

// Packed f32x2 FMA
#define FMA2(acc, a, b) \
    asm("fma.rn.f32x2 %0, %1, %2, %0;" : "+l"(acc) : "l"(a), "l"(b))

__device__ __forceinline__ float pair_sum(unsigned long long u) {
    float lo = __uint_as_float((unsigned)(u & 0xffffffffu));
    float hi = __uint_as_float((unsigned)(u >> 32));
    return lo + hi;
}

#define WARP_RED_SUM(v)                                   \
  do {                                                    \
    v += __shfl_xor_sync(0xffffffffu, v, 16);             \
    v += __shfl_xor_sync(0xffffffffu, v, 8);              \
    v += __shfl_xor_sync(0xffffffffu, v, 4);              \
    v += __shfl_xor_sync(0xffffffffu, v, 2);              \
    v += __shfl_xor_sync(0xffffffffu, v, 1);              \
  } while (0)

// ---------------------------------------------------------------------------
// Prep kernel: one block per batch. Transposes x[b] ([m][a] flat) into
// g_xt[b][a][m], and performs the ENTIRE iteration-0 fused step (uniform c):
// y0 = mean_m x, s0 = W y0, v0 = squash(s0), wv0 = W^T v0 -> g_wv.
// ---------------------------------------------------------------------------
#define P_THREADS 320

__global__ void __launch_bounds__(P_THREADS)
prep_kernel(const float* __restrict__ x, const float* __restrict__ W)
{
    __shared__ float xsm[MUL * 9];            // padded rows [m][9]
    __shared__ float wsm[NK * NO * AIN];
    __shared__ float y0[AIN];
    __shared__ float ssm[NK * NO];
    __shared__ float csm[NO];

    const int tid = threadIdx.x;
    const int b   = blockIdx.x;

    const float4* xsrc = (const float4*)(x + (size_t)b * (MUL * AIN));
    for (int i = tid; i < MUL * 2; i += P_THREADS) {
        float4 v = xsrc[i];
        int m = i >> 1, h = i & 1;
        float* d = xsm + m * 9 + h * 4;
        d[0] = v.x; d[1] = v.y; d[2] = v.z; d[3] = v.w;
    }
    for (int i = tid; i < NK * NO * AIN / 4; i += P_THREADS)
        ((float4*)wsm)[i] = ((const float4*)W)[i];
    __syncthreads();

    // transposed planes out (coalesced float4)
    float4* xdst = (float4*)(g_xt + (size_t)b * (MUL * AIN));
    for (int i = tid; i < MUL * 2; i += P_THREADS) {
        int a = i >> 8, q = i & 255, m4 = q * 4;
        float4 v;
        v.x = xsm[(m4 + 0) * 9 + a];
        v.y = xsm[(m4 + 1) * 9 + a];
        v.z = xsm[(m4 + 2) * 9 + a];
        v.w = xsm[(m4 + 3) * 9 + a];
        xdst[a * 256 + q] = v;
    }

    // y0 = mean over m
    {
        int w = tid >> 5, lane = tid & 31;
        if (w < 8) {
            float s = 0.f;
            #pragma unroll 8
            for (int t = 0; t < 32; t++) s += xsm[(t * 32 + lane) * 9 + w];
            WARP_RED_SUM(s);
            if (lane == 0) y0[w] = s * (1.0f / 1024.0f);
        }
    }
    __syncthreads();

    const int k = tid >> 4, o = tid & 15;
    const float* wk = wsm + (k * NO + o) * AIN;
    float s = 0.f;
    #pragma unroll
    for (int a = 0; a < AIN; a++) s += wk[a] * y0[a];
    ssm[tid] = s;
    __syncthreads();

    if (tid < NO) {
        float msq = 0.f;
        #pragma unroll
        for (int kk = 0; kk < NK; kk++) {
            float t = ssm[kk * NO + tid];
            msq += t * t;
        }
        csm[tid] = msq / ((1.f + msq) * sqrtf(msq));
    }
    __syncthreads();

    float v = csm[o] * s;
    ssm[tid] = v;
    __syncthreads();

    if (tid < NK * AIN) {
        int kk = tid >> 3, aa = tid & 7;
        float acc = 0.f;
        #pragma unroll
        for (int oo = 0; oo < NO; oo++)
            acc += wsm[(kk * NO + oo) * AIN + aa] * ssm[kk * NO + oo];
        g_wv[(size_t)b * (NK * AIN) + tid] = acc;
    }
}

// ---------------------------------------------------------------------------
// Fused kernel (iterations 1,2): y = c^T x, s = W y, v = squash(s), wv or out.
// One block per batch, 320 threads. warp = (kquad, a-half): acc[4][4] u64 = 32
// regs (no spill); each x LDS.128 feeds 4 classes (x-LDS halved vs R6).
// ---------------------------------------------------------------------------
#define F_THREADS 320

__global__ void __launch_bounds__(F_THREADS, 2)
fused_kernel(const float* __restrict__ W, float* __restrict__ out, int final_iter)
{
    __shared__ float xs[AIN * PL];            // 33.3 KB planes [a][m]
    __shared__ float ysm[NK * AIN];
    __shared__ float ssm[NK * NO];
    __shared__ float csm[NO];

    const int tid = threadIdx.x;
    const int B   = blockIdx.x;

    // stage x planes (pure float4 copy from pre-transposed g_xt)
    {
        const float4* xsrc = (const float4*)(g_xt + (size_t)B * 8192);
        for (int i = tid; i < 2048; i += F_THREADS) {
            int a = i >> 8, q = i & 255;
            *(float4*)(xs + a * PL + q * 4) = xsrc[i];
        }
    }
    __syncthreads();

    // ---- y phase: warp = (kq, ah); 4 classes x 4 atoms per thread ----
    {
        const int w = tid >> 5, lane = tid & 31;
        const int k0 = (w >> 1) * 4;
        const int a0 = (w & 1) * 4;

        unsigned long long acc[4][4];
        #pragma unroll
        for (int kk = 0; kk < 4; kk++)
            #pragma unroll
            for (int aa = 0; aa < 4; aa++) acc[kk][aa] = 0ull;

        #pragma unroll 2
        for (int j = 0; j < 8; j++) {
            const int m = j * 128 + lane * 4;
            ulonglong2 ck0 = *(const ulonglong2*)(g_c + (k0 + 0) * MUL + m);
            ulonglong2 ck1 = *(const ulonglong2*)(g_c + (k0 + 1) * MUL + m);
            ulonglong2 ck2 = *(const ulonglong2*)(g_c + (k0 + 2) * MUL + m);
            ulonglong2 ck3 = *(const ulonglong2*)(g_c + (k0 + 3) * MUL + m);
            #pragma unroll
            for (int aa = 0; aa < 4; aa++) {
                ulonglong2 xv = *(const ulonglong2*)(xs + (a0 + aa) * PL + m);
                FMA2(acc[0][aa], ck0.x, xv.x); FMA2(acc[0][aa], ck0.y, xv.y);
                FMA2(acc[1][aa], ck1.x, xv.x); FMA2(acc[1][aa], ck1.y, xv.y);
                FMA2(acc[2][aa], ck2.x, xv.x); FMA2(acc[2][aa], ck2.y, xv.y);
                FMA2(acc[3][aa], ck3.x, xv.x); FMA2(acc[3][aa], ck3.y, xv.y);
            }
        }
        #pragma unroll
        for (int kk = 0; kk < 4; kk++) {
            #pragma unroll
            for (int aa = 0; aa < 4; aa++) {
                float v = pair_sum(acc[kk][aa]);
                WARP_RED_SUM(v);
                if (lane == 0) ysm[(k0 + kk) * AIN + a0 + aa] = v;
            }
        }
    }
    __syncthreads();

    // ---- s / squash / v / wv ----
    const int k = tid >> 4, o = tid & 15;
    const float* wk = W + (size_t)tid * AIN;   // (k*NO+o)*AIN == tid*8, coalesced
    const float* yk = ysm + k * AIN;
    float s = 0.f;
    #pragma unroll
    for (int a = 0; a < AIN; a++) s += wk[a] * yk[a];
    ssm[tid] = s;
    __syncthreads();

    if (tid < NO) {
        float msq = 0.f;
        #pragma unroll
        for (int kk = 0; kk < NK; kk++) {
            float t = ssm[kk * NO + tid];
            msq += t * t;
        }
        csm[tid] = msq / ((1.f + msq) * sqrtf(msq));
    }
    __syncthreads();

    float v = csm[o] * s;
    if (final_iter) out[(size_t)B * (NK * NO) + tid] = v;   // coalesced
    ssm[tid] = v;
    __syncthreads();

    if (!final_iter && tid < NK * AIN) {
        int kk = tid >> 3, aa = tid & 7;
        float acc = 0.f;
        #pragma unroll
        for (int oo = 0; oo < NO; oo++)
            acc += W[(kk * NO + oo) * AIN + aa] * ssm[kk * NO + oo];
        g_wv[(size_t)B * (NK * AIN) + tid] = acc;
    }
}

// ---------------------------------------------------------------------------
// Update kernel: 256 blocks = (16 m-tiles x 16 slices of 16 batches).
// partial[m,k] = sum_{b in slice} sum_a x[b,m,a]*wv[b,k,a] / 256
// ---------------------------------------------------------------------------
#define U_THREADS 320

__global__ void __launch_bounds__(U_THREADS)
update_kernel(const float* __restrict__ x)
{
    __shared__ float xsU[8 * 512];
    __shared__ float wvs[8 * 160];

    const int tid   = threadIdx.x;
    const int m0    = blockIdx.x * 64;
    const int bbase = blockIdx.y * 16;
    const int mi4   = tid / NK;
    const int k     = tid % NK;

    unsigned long long acc[4];
    #pragma unroll
    for (int i = 0; i < 4; i++) acc[i] = 0ull;

    for (int c0 = 0; c0 < 16; c0 += 8) {
        __syncthreads();
        for (int i = tid; i < 1024; i += U_THREADS) {
            int bi = i >> 7, rr = i & 127;
            ((float4*)(xsU + bi * 512))[rr] =
                ((const float4*)(x + (size_t)(bbase + c0 + bi) * 8192 + m0 * 8))[rr];
        }
        for (int i = tid; i < 320; i += U_THREADS) {
            int bi = i / 40, rr = i % 40;
            ((float4*)(wvs + bi * 160))[rr] =
                ((const float4*)(g_wv + (size_t)(bbase + c0 + bi) * 160))[rr];
        }
        __syncthreads();

        #pragma unroll
        for (int bi = 0; bi < 8; bi++) {
            const ulonglong2* wp = (const ulonglong2*)(wvs + bi * 160 + k * AIN);
            ulonglong2 wA = wp[0], wB = wp[1];
            const ulonglong2* xp = (const ulonglong2*)(xsU + bi * 512 + mi4 * 32);
            #pragma unroll
            for (int mm = 0; mm < 4; mm++) {
                ulonglong2 xA = xp[mm * 2];
                ulonglong2 xB = xp[mm * 2 + 1];
                FMA2(acc[mm], xA.x, wA.x);
                FMA2(acc[mm], xA.y, wA.y);
                FMA2(acc[mm], xB.x, wB.x);
                FMA2(acc[mm], xB.y, wB.y);
            }
        }
    }

    float* dst = g_bpart + (size_t)blockIdx.y * (NK * MUL) + k * MUL + m0 + mi4 * 4;
    #pragma unroll
    for (int mm = 0; mm < 4; mm++) dst[mm] = pair_sum(acc[mm]) * (1.0f / 256.0f);
}

// ---------------------------------------------------------------------------
// Softmax kernel: 20 blocks x 1024 threads (thread per m).
// Combine 16 partials -> b (optionally accumulate), softmax over m -> c.
// ---------------------------------------------------------------------------
__global__ void __launch_bounds__(1024)
softmax_kernel(int accum)
{
    const int k = blockIdx.x;
    const int t = threadIdx.x;
    const int lane = t & 31, wp = t >> 5;
    __shared__ float red[32];
    __shared__ float bc;

    float b = accum ? g_b[k * MUL + t] : 0.f;
    #pragma unroll
    for (int p = 0; p < 16; p++) b += g_bpart[p * NK * MUL + k * MUL + t];
    g_b[k * MUL + t] = b;

    float mx = b;
    #pragma unroll
    for (int off = 16; off; off >>= 1)
        mx = fmaxf(mx, __shfl_xor_sync(0xffffffffu, mx, off));
    if (lane == 0) red[wp] = mx;
    __syncthreads();
    if (t < 32) {
        float m = red[t];
        #pragma unroll
        for (int off = 16; off; off >>= 1)
            m = fmaxf(m, __shfl_xor_sync(0xffffffffu, m, off));
        if (t == 0) bc = m;
    }
    __syncthreads();
    mx = bc;

    float e = expf(b - mx);
    float s = e;
    #pragma unroll
    for (int off = 16; off; off >>= 1)
        s += __shfl_xor_sync(0xffffffffu, s, off);
    __syncthreads();
    if (lane == 0) red[wp] = s;
    __syncthreads();
    if (t < 32) {
        float ss = red[t];
        #pragma unroll
        for (int off = 16; off; off >>= 1)
            ss += __shfl_xor_sync(0xffffffffu, ss, off);
        if (t == 0) bc = ss;
    }
    __syncthreads();

    g_c[k * MUL + t] = e * (1.0f / bc);
}

// ---------------------------------------------------------------------------
extern "C" void kernel_launch(void* const* d_in, const int* in_sizes, int n_in,
                              void* d_out, int out_size)
{
    const float* x = (const float*)d_in[0];   // [256][1024][8] flat view
    const float* W = (const float*)d_in[1];   // [20][16][8]
    float* out = (float*)d_out;               // [256][20][16][1]

    dim3 ugrid(16, 16);

    // iter 0 folded into prep (uniform c): transpose + y0/s0/v0/wv0
    prep_kernel<<<B_TOT, P_THREADS>>>(x, W);
    update_kernel<<<ugrid, U_THREADS>>>(x);
    softmax_kernel<<<NK, 1024>>>(0);

    // iteration 1
    fused_kernel<<<B_TOT, F_THREADS>>>(W, out, 0);
    update_kernel<<<ugrid, U_THREADS>>>(x);
    softmax_kernel<<<NK, 1024>>>(1);

    // iteration 2 (final -> write v)
    fused_kernel<<<B_TOT, F_THREADS>>>(W, out, 1);
}